// round 15
// baseline (speedup 1.0000x reference)
#include <cuda_runtime.h>
#include <cuda_bf16.h>
#include <cuda_fp16.h>
#include <cstdint>

// Problem dims (fixed by the dataset)
#define Vv 32000
#define Ee 1024
#define Hh 1024
#define Ll 2
#define Bb 64
#define Tt 512
#define G3 (3*Hh)

// Output packing: (out [1,B,H]) (hidden [L,B,H]) (hiddens [B,T,H])
#define OUT_OFF  0
#define HID_OFF  (Bb*Hh)
#define HIDS_OFF (Bb*Hh + Ll*Bb*Hh)

// Persistent recurrence partitioning: 128 blocks = 32 n-tiles x 4 k-splits
#define RGRID 128
#define RTN   96             // cols per n-tile (32*96 = 3072)
#define RKT   4              // k-splits
#define RKC   256            // k per split (4*256 = 1024)

// warp-MMA GEMM tiling (input-side)
#define MT_M 128
#define MT_N 128
#define KCH  64
#define NPASS 2              // fp16 hi*hi + bf16 lo*W
#define PADU 9               // uint4 per padded smem row (144B, conflict-free)
#define GSTG 18432           // bytes per A (or B) stage: 128 rows * 144B
#define NSTAGE 3

// recurrence smem row stride: 32 uint4 padded to 33 (528B, odd -> conflict-free)
#define PRU 33

// Scratch (device globals: allocation-free per harness rules)
__device__ float g_gx[(size_t)Tt * Bb * G3];
__device__ float g_part[(size_t)RKT * Bb * G3];
__device__ float g_h[Ll * Bb * Hh];
__device__ uint16_t g_Hhi[Ll * Bb * Hh];           // fp16(h)  (producer-side split)
__device__ uint16_t g_Hlo[Ll * Bb * Hh];           // bf16(h - fp16(h))
__device__ uint16_t g_Ahi[(size_t)Tt * Bb * Ee];   // fp16(A)
__device__ uint16_t g_Alo[(size_t)Tt * Bb * Ee];   // bf16(A - fp16(A))
__device__ uint16_t g_Whi[(size_t)G3 * Ee];        // fp16(W)
__device__ uint16_t g_Wbf[(size_t)G3 * Ee];        // bf16(W)

// Grid barrier state (monotonic release counter)
__device__ unsigned g_bar_arrive = 0;
__device__ unsigned g_bar_release = 0;

// ---------------------------------------------------------------------------
// PTX helpers
// ---------------------------------------------------------------------------
__device__ __forceinline__ uint32_t smem_u32(const void* p) {
    uint32_t a;
    asm("{ .reg .u64 t; cvta.to.shared.u64 t, %1; cvt.u32.u64 %0, t; }" : "=r"(a) : "l"(p));
    return a;
}
#define LDSM_X4(r0, r1, r2, r3, a) \
    asm volatile("ldmatrix.sync.aligned.m8n8.x4.shared.b16 {%0,%1,%2,%3}, [%4];" \
                 : "=r"(r0), "=r"(r1), "=r"(r2), "=r"(r3) : "r"(a))
#define MMA_BF16(d, a, b0, b1) \
    asm volatile("mma.sync.aligned.m16n8k16.row.col.f32.bf16.bf16.f32 " \
                 "{%0,%1,%2,%3}, {%4,%5,%6,%7}, {%8,%9}, {%0,%1,%2,%3};" \
                 : "+f"((d)[0]), "+f"((d)[1]), "+f"((d)[2]), "+f"((d)[3]) \
                 : "r"((a)[0]), "r"((a)[1]), "r"((a)[2]), "r"((a)[3]), \
                   "r"(b0), "r"(b1))
#define MMA_F16(d, a, b0, b1) \
    asm volatile("mma.sync.aligned.m16n8k16.row.col.f32.f16.f16.f32 " \
                 "{%0,%1,%2,%3}, {%4,%5,%6,%7}, {%8,%9}, {%0,%1,%2,%3};" \
                 : "+f"((d)[0]), "+f"((d)[1]), "+f"((d)[2]), "+f"((d)[3]) \
                 : "r"((a)[0]), "r"((a)[1]), "r"((a)[2]), "r"((a)[3]), \
                   "r"(b0), "r"(b1))
#define CP_ASYNC16(dst, src) \
    asm volatile("cp.async.cg.shared.global [%0], [%1], 16;" :: "r"(dst), "l"(src) : "memory")
#define CP_COMMIT  asm volatile("cp.async.commit_group;" ::: "memory")
#define CP_WAIT1   asm volatile("cp.async.wait_group 1;" ::: "memory")
#define CP_WAIT0   asm volatile("cp.async.wait_group 0;" ::: "memory")

__device__ __forceinline__ uint32_t pk_bf2(float lo, float hi) {
    __nv_bfloat162 t = __floats2bfloat162_rn(lo, hi);
    return *reinterpret_cast<uint32_t*>(&t);
}
__device__ __forceinline__ uint32_t pk_h2(float lo, float hi) {
    __half2 t = __floats2half2_rn(lo, hi);
    return *reinterpret_cast<uint32_t*>(&t);
}

// Split grid barrier (monotonic counter; base read at kernel start)
__device__ __forceinline__ void bar_arrive() {
    __syncthreads();
    if (threadIdx.x == 0) {
        __threadfence();
        unsigned a = atomicAdd(&g_bar_arrive, 1u);
        if (a == RGRID - 1) {
            g_bar_arrive = 0;
            __threadfence();
            atomicAdd(&g_bar_release, 1u);
        }
    }
}
__device__ __forceinline__ void bar_wait(unsigned target) {
    if (threadIdx.x == 0) {
        while ((int)(*(volatile unsigned*)&g_bar_release - target) < 0) __nanosleep(32);
        __threadfence();
    }
    __syncthreads();
}

// ---------------------------------------------------------------------------
// Embedding with fused fp16/bf16 split
// ---------------------------------------------------------------------------
__global__ void embed_split(const int* __restrict__ x, const float* __restrict__ emb) {
    int row = blockIdx.x;          // t*B + b
    int t = row / Bb;
    int b = row - t * Bb;
    int tok = x[b * Tt + t];
    float4 v = reinterpret_cast<const float4*>(emb + (size_t)tok * Ee)[threadIdx.x];
    float hx = __half2float(__float2half_rn(v.x));
    float hy = __half2float(__float2half_rn(v.y));
    float hz = __half2float(__float2half_rn(v.z));
    float hw = __half2float(__float2half_rn(v.w));
    uint2 wh = make_uint2(pk_h2(hx, hy), pk_h2(hz, hw));
    uint2 wl = make_uint2(pk_bf2(v.x - hx, v.y - hy), pk_bf2(v.z - hz, v.w - hw));
    size_t base = (size_t)row * Ee + threadIdx.x * 4;
    *reinterpret_cast<uint2*>(g_Ahi + base) = wh;
    *reinterpret_cast<uint2*>(g_Alo + base) = wl;
}

__global__ void init_h(const float* __restrict__ h0) {
    int i = blockIdx.x * blockDim.x + threadIdx.x;
    if (i < Ll * Bb * Hh) {
        float v = h0[i];
        g_h[i] = v;
        __half hh = __float2half_rn(v);
        float hf = __half2float(hh);
        __nv_bfloat16 lo = __float2bfloat16(v - hf);
        g_Hhi[i] = *reinterpret_cast<uint16_t*>(&hh);
        g_Hlo[i] = *reinterpret_cast<uint16_t*>(&lo);
    }
}

__global__ void conv_split_W(const float* __restrict__ src) {
    size_t i = (size_t)blockIdx.x * 256 + threadIdx.x;
    float x = src[i];
    __half h = __float2half_rn(x);
    __nv_bfloat16 b = __float2bfloat16(x);
    g_Whi[i] = *reinterpret_cast<uint16_t*>(&h);
    g_Wbf[i] = *reinterpret_cast<uint16_t*>(&b);
}

// ---------------------------------------------------------------------------
// 2-pass split TN GEMM via mma.sync, 3-stage cp.async pipeline (unchanged).
// ---------------------------------------------------------------------------
extern __shared__ __align__(16) unsigned char s_raw[];

__global__ __launch_bounds__(256, 2) void gemm_gx_mma(const float* __restrict__ bias) {
    const int tid = threadIdx.x;
    const int wid = tid >> 5, lane = tid & 31;
    const int m0 = blockIdx.y * MT_M;
    const int n0 = blockIdx.x * MT_N;
    const int wm = (wid >> 2) * 64;
    const int wn = (wid & 3) * 32;

    const uint32_t sbase = smem_u32(s_raw);
    const int strow = tid >> 3;
    const int stcol = tid & 7;
    const int lrow = lane & 15;
    const int lcol = lane >> 4;

    float acc[4][4][4];
#pragma unroll
    for (int i = 0; i < 4; i++)
#pragma unroll
        for (int j = 0; j < 4; j++)
#pragma unroll
            for (int r = 0; r < 4; r++) acc[i][j][r] = 0.f;

    auto issue_chunk = [&](int c, int s) {
        int pass = c >> 4, cc = c & 15;
        const uint16_t* Asrc = pass ? g_Alo : g_Ahi;
        const uint16_t* Bsrc = pass ? g_Wbf : g_Whi;
#pragma unroll
        for (int i = 0; i < 4; i++) {
            int r = strow + 32 * i;
            const uint16_t* ga = Asrc + (size_t)(m0 + r) * Ee + cc * KCH + stcol * 8;
            const uint16_t* gb = Bsrc + (size_t)(n0 + r) * Ee + cc * KCH + stcol * 8;
            uint32_t off = (uint32_t)(r * PADU + stcol) * 16 + s * GSTG;
            CP_ASYNC16(sbase + off, ga);
            CP_ASYNC16(sbase + NSTAGE * GSTG + off, gb);
        }
    };

    issue_chunk(0, 0);
    CP_COMMIT;
    issue_chunk(1, 1);
    CP_COMMIT;

    const int NCH = NPASS * 16;      // 32
    for (int c = 0; c < NCH; c++) {
        if (c < NCH - 2) CP_WAIT1; else CP_WAIT0;
        __syncthreads();
        if (c < NCH - 2) {
            issue_chunk(c + 2, (c + 2) % NSTAGE);
            CP_COMMIT;
        }

        const uint32_t sa = sbase + (c % NSTAGE) * GSTG;
        const uint32_t sb = sbase + NSTAGE * GSTG + (c % NSTAGE) * GSTG;
#pragma unroll
        for (int k16 = 0; k16 < KCH / 16; k16++) {
            uint32_t af[4][4];
#pragma unroll
            for (int mt = 0; mt < 4; mt++) {
                uint32_t addr = sa + ((wm + mt * 16 + lrow) * PADU + k16 * 2 + lcol) * 16;
                LDSM_X4(af[mt][0], af[mt][1], af[mt][2], af[mt][3], addr);
            }
            uint32_t bf[2][4];
#pragma unroll
            for (int bt = 0; bt < 2; bt++) {
                uint32_t addr = sb + ((wn + bt * 16 + lrow) * PADU + k16 * 2 + lcol) * 16;
                LDSM_X4(bf[bt][0], bf[bt][1], bf[bt][2], bf[bt][3], addr);
            }
            if (c < 16) {
#pragma unroll
                for (int mt = 0; mt < 4; mt++)
#pragma unroll
                    for (int nt = 0; nt < 4; nt++) {
                        int bt = nt >> 1, lh = nt & 1;
                        MMA_F16(acc[mt][nt], af[mt], bf[bt][lh], bf[bt][lh + 2]);
                    }
            } else {
#pragma unroll
                for (int mt = 0; mt < 4; mt++)
#pragma unroll
                    for (int nt = 0; nt < 4; nt++) {
                        int bt = nt >> 1, lh = nt & 1;
                        MMA_BF16(acc[mt][nt], af[mt], bf[bt][lh], bf[bt][lh + 2]);
                    }
            }
        }
    }

    // Epilogue: fragment layout -> gmem with bias
    const int er = lane >> 2;
    const int ec = (lane & 3) * 2;
#pragma unroll
    for (int mt = 0; mt < 4; mt++) {
#pragma unroll
        for (int half = 0; half < 2; half++) {
            int grow = m0 + wm + mt * 16 + er + half * 8;
            size_t base = (size_t)grow * G3;
#pragma unroll
            for (int nt = 0; nt < 4; nt++) {
                int gcol = n0 + wn + nt * 8 + ec;
                float2 v;
                v.x = acc[mt][nt][half * 2 + 0] + bias[gcol];
                v.y = acc[mt][nt][half * 2 + 1] + bias[gcol + 1];
                *reinterpret_cast<float2*>(&g_gx[base + gcol]) = v;
            }
        }
    }
}

// ---------------------------------------------------------------------------
// Persistent recurrence kernel: 2-pass HMMA, producer-side h split,
// cp.async staging (no per-step conversion).
// Block (kt = bid>>5, nt = bid&31). Smem 168960B.
// ---------------------------------------------------------------------------
__global__ __launch_bounds__(256, 1) void gru_layer_persist(
    int l, const float* __restrict__ Whh_all, const float* __restrict__ bhh_all,
    float* __restrict__ dout) {

    uint4* s4 = reinterpret_cast<uint4*>(s_raw);
    uint16_t* sH16 = reinterpret_cast<uint16_t*>(s4 + 0);       // 64*33 u4
    uint16_t* sHlb = reinterpret_cast<uint16_t*>(s4 + 2112);    // 64*33 u4
    uint16_t* sW16 = reinterpret_cast<uint16_t*>(s4 + 4224);    // 96*33 u4
    uint16_t* sWb  = reinterpret_cast<uint16_t*>(s4 + 7392);    // 96*33 u4

    const int tid = threadIdx.x;
    const int bid = blockIdx.x;
    const int wid = tid >> 5, lane = tid & 31;
    const int nt = bid & 31;
    const int kt = bid >> 5;
    const int n0g = nt * RTN;
    const int k0 = kt * RKC;

    const float* W = Whh_all + (size_t)l * G3 * Hh;
    const float* bhh = bhh_all + l * G3;
    const float* hbase = g_h + l * Bb * Hh;
    const uint16_t* hb16 = g_Hhi + l * Bb * Hh;
    const uint16_t* hblo = g_Hlo + l * Bb * Hh;

    __shared__ unsigned s_base0;
    if (tid == 0) s_base0 = *(volatile unsigned*)&g_bar_release;

    // ---- startup: W slice [96 x 256] -> fp16 + bf16 in smem ----
    for (int f = tid; f < RTN * 64; f += 256) {
        int r = f >> 6;          // 0..95
        int c4 = f & 63;         // float4 col 0..63
        float4 v = *reinterpret_cast<const float4*>(&W[(size_t)(n0g + r) * Hh + k0 + c4 * 4]);
        uint32_t* dh = reinterpret_cast<uint32_t*>(sW16) + r * (PRU * 4) + c4 * 2;
        uint32_t* db = reinterpret_cast<uint32_t*>(sWb)  + r * (PRU * 4) + c4 * 2;
        dh[0] = pk_h2(v.x, v.y);
        dh[1] = pk_h2(v.z, v.w);
        db[0] = pk_bf2(v.x, v.y);
        db[1] = pk_bf2(v.z, v.w);
    }
    __syncthreads();
    const unsigned bar_base = s_base0;
    unsigned gen = 0;

    const uint32_t aH16 = smem_u32(sH16), aHlb = smem_u32(sHlb);
    const uint32_t aW16 = smem_u32(sW16), aWb = smem_u32(sWb);

    const int wb = (wid >> 1) * 16;    // batch base: 0,16,32,48
    const int wn = (wid & 1) * 48;     // col base within tile: 0,48
    const int lrow = lane & 15;
    const int lcol = lane >> 4;
    const int er = lane >> 2;
    const int ec = (lane & 3) * 2;

    // gate-phase constants
    int e_[2], b_[2], j_[2];
    float br_[2], bz_[2], bn_[2];
#pragma unroll
    for (int ei = 0; ei < 2; ei++) {
        e_[ei] = bid * 512 + ei * 256 + tid;
        b_[ei] = e_[ei] >> 10;
        j_[ei] = e_[ei] & 1023;
        br_[ei] = bhh[j_[ei]];
        bz_[ei] = bhh[Hh + j_[ei]];
        bn_[ei] = bhh[2 * Hh + j_[ei]];
    }

    for (int t = 0; t < Tt; t++) {
        // ---- stage h slice [64 x 256] via cp.async (pre-split at producer) ----
        __syncthreads();
#pragma unroll
        for (int i = 0; i < 8; i++) {
            int f = tid + i * 256;       // 0..2047
            int b = f >> 5;              // 0..63
            int c = f & 31;              // uint4 col within slice
            size_t srco = (size_t)b * Hh + k0 + c * 8;
            uint32_t dsto = (uint32_t)(b * PRU + c) * 16;
            CP_ASYNC16(aH16 + dsto, hb16 + srco);
            CP_ASYNC16(aHlb + dsto, hblo + srco);
        }
        CP_COMMIT;
        CP_WAIT0;
        __syncthreads();

        // ---- 2-pass HMMA: gh[b, n] = sum_k h[b,k] * W[n,k] ----
        float acc[6][4];
#pragma unroll
        for (int j = 0; j < 6; j++)
#pragma unroll
            for (int r = 0; r < 4; r++) acc[j][r] = 0.f;

#pragma unroll
        for (int pass = 0; pass < 2; pass++) {
            const uint32_t aBase = pass ? aHlb : aH16;
            const uint32_t bBase = pass ? aWb : aW16;
#pragma unroll
            for (int k16 = 0; k16 < RKC / 16; k16++) {
                uint32_t af[4];
                {
                    uint32_t addr = aBase + ((wb + lrow) * PRU + k16 * 2 + lcol) * 16;
                    LDSM_X4(af[0], af[1], af[2], af[3], addr);
                }
                uint32_t bfr[3][4];
#pragma unroll
                for (int bt = 0; bt < 3; bt++) {
                    uint32_t addr = bBase + ((wn + bt * 16 + lrow) * PRU + k16 * 2 + lcol) * 16;
                    LDSM_X4(bfr[bt][0], bfr[bt][1], bfr[bt][2], bfr[bt][3], addr);
                }
                if (pass == 0) {
#pragma unroll
                    for (int ntl = 0; ntl < 6; ntl++) {
                        int bt = ntl >> 1, lh = ntl & 1;
                        MMA_F16(acc[ntl], af, bfr[bt][lh], bfr[bt][lh + 2]);
                    }
                } else {
#pragma unroll
                    for (int ntl = 0; ntl < 6; ntl++) {
                        int bt = ntl >> 1, lh = ntl & 1;
                        MMA_BF16(acc[ntl], af, bfr[bt][lh], bfr[bt][lh + 2]);
                    }
                }
            }
        }

        // ---- write partials: g_part[kt][b][n0g + wn + ntl*8 + ec] ----
#pragma unroll
        for (int half = 0; half < 2; half++) {
            int b = wb + er + half * 8;
            size_t rowbase = ((size_t)kt * Bb + b) * G3 + n0g + wn;
#pragma unroll
            for (int ntl = 0; ntl < 6; ntl++) {
                float2 v;
                v.x = acc[ntl][half * 2 + 0];
                v.y = acc[ntl][half * 2 + 1];
                *reinterpret_cast<float2*>(&g_part[rowbase + ntl * 8 + ec]) = v;
            }
        }

        bar_arrive();   // barrier 1 arrive
        ++gen;

        // prefetch gate inputs (block-private elements; race-free)
        float xr_[2], xz_[2], xn_[2], hold_[2];
#pragma unroll
        for (int ei = 0; ei < 2; ei++) {
            size_t gxb = ((size_t)t * Bb + b_[ei]) * G3;
            xr_[ei] = g_gx[gxb + j_[ei]];
            xz_[ei] = g_gx[gxb + Hh + j_[ei]];
            xn_[ei] = g_gx[gxb + 2 * Hh + j_[ei]];
            hold_[ei] = hbase[e_[ei]];
        }

        bar_wait(bar_base + gen);   // barrier 1 wait (partials visible)

        // ---- fused reduce + gates + state update ----
#pragma unroll
        for (int ei = 0; ei < 2; ei++) {
            int b = b_[ei], j = j_[ei];
            float hr = br_[ei], hz = bz_[ei], hn = bn_[ei];
#pragma unroll
            for (int ks = 0; ks < RKT; ks++) {
                size_t base = ((size_t)ks * Bb + b) * G3;
                hr += g_part[base + j];
                hz += g_part[base + Hh + j];
                hn += g_part[base + 2 * Hh + j];
            }

            float rg = 1.f / (1.f + expf(-(xr_[ei] + hr)));
            float zg = 1.f / (1.f + expf(-(xz_[ei] + hz)));
            float ng = tanhf(xn_[ei] + rg * hn);

            float hnew = (1.f - zg) * ng + zg * hold_[ei];
            g_h[l * Bb * Hh + e_[ei]] = hnew;

            // producer-side fp16/bf16 split (once per element)
            __half hh = __float2half_rn(hnew);
            float hf = __half2float(hh);
            __nv_bfloat16 lo = __float2bfloat16(hnew - hf);
            uint16_t hb = *reinterpret_cast<uint16_t*>(&hh);
            uint16_t lb = *reinterpret_cast<uint16_t*>(&lo);
            g_Hhi[l * Bb * Hh + e_[ei]] = hb;
            g_Hlo[l * Bb * Hh + e_[ei]] = lb;

            if (l == 0) {
                size_t arow = ((size_t)t * Bb + b) * Ee + j;
                g_Ahi[arow] = hb;
                g_Alo[arow] = lb;
                dout[HIDS_OFF + ((size_t)b * Tt + t) * Hh + j] = hnew;
            }
        }

        bar_arrive();   // barrier 2
        ++gen;
        bar_wait(bar_base + gen);
    }
}

__global__ void finalize(float* __restrict__ dout) {
    int i = blockIdx.x * blockDim.x + threadIdx.x;
    float h0f = g_h[i];
    float h1f = g_h[Bb * Hh + i];
    dout[OUT_OFF + i] = h1f;
    dout[HID_OFF + i] = h0f;
    dout[HID_OFF + Bb * Hh + i] = h1f;
}

// ---------------------------------------------------------------------------
extern "C" void kernel_launch(void* const* d_in, const int* in_sizes, int n_in,
                              void* d_out, int out_size) {
    const int*   x   = (const int*)d_in[0];
    const float* h0  = (const float*)d_in[1];
    const float* emb = (const float*)d_in[2];
    const float* Wih = (const float*)d_in[3];
    const float* Whh = (const float*)d_in[4];
    const float* bih = (const float*)d_in[5];
    const float* bhh = (const float*)d_in[6];
    float* out = (float*)d_out;

    const int gemm_smem = 2 * NSTAGE * GSTG;                    // 110592
    const int rec_smem = (64 + 64 + 96 + 96) * PRU * 16;        // 168960
    cudaFuncSetAttribute(gemm_gx_mma,
                         cudaFuncAttributeMaxDynamicSharedMemorySize, gemm_smem);
    cudaFuncSetAttribute(gru_layer_persist,
                         cudaFuncAttributeMaxDynamicSharedMemorySize, rec_smem);

    init_h<<<(Ll * Bb * Hh + 255) / 256, 256>>>(h0);
    embed_split<<<Tt * Bb, Ee / 4>>>(x, emb);

    dim3 tgrid(G3 / MT_N, (Tt * Bb) / MT_M);    // (24, 256)
    const int nW = (G3 * Ee) / 256;

    // Layer 0
    conv_split_W<<<nW, 256>>>(Wih);
    gemm_gx_mma<<<tgrid, 256, gemm_smem>>>(bih);
    gru_layer_persist<<<RGRID, 256, rec_smem>>>(0, Whh, bhh, out);

    // Layer 1 (A = fp16/bf16 split of layer-0 states, written by the gate phase)
    conv_split_W<<<nW, 256>>>(Wih + (size_t)G3 * Ee);
    gemm_gx_mma<<<tgrid, 256, gemm_smem>>>(bih + G3);
    gru_layer_persist<<<RGRID, 256, rec_smem>>>(1, Whh, bhh, out);

    finalize<<<(Bb * Hh) / 256, 256>>>(out);
}

// round 17
// speedup vs baseline: 1.0976x; 1.0976x over previous
#include <cuda_runtime.h>
#include <cuda_bf16.h>
#include <cuda_fp16.h>
#include <cstdint>

// Problem dims (fixed by the dataset)
#define Vv 32000
#define Ee 1024
#define Hh 1024
#define Ll 2
#define Bb 64
#define Tt 512
#define G3 (3*Hh)

// Output packing: (out [1,B,H]) (hidden [L,B,H]) (hiddens [B,T,H])
#define OUT_OFF  0
#define HID_OFF  (Bb*Hh)
#define HIDS_OFF (Bb*Hh + Ll*Bb*Hh)

// Persistent recurrence partitioning: 128 blocks = 2 b-halves x 64 col-groups
#define RGRID 128

// warp-MMA GEMM tiling (input-side)
#define MT_M 128
#define MT_N 128
#define KCH  64
#define NPASS 2              // fp16 hi*hi + bf16 lo*W
#define PADU 9               // uint4 per padded smem row (144B, conflict-free)
#define GSTG 18432           // bytes per A (or B) stage: 128 rows * 144B
#define NSTAGE 3

// Scratch (device globals: allocation-free per harness rules)
__device__ float g_gx[(size_t)Tt * Bb * G3];
__device__ float g_h[Ll * Bb * Hh];
__device__ uint16_t g_Hhi[Ll * Bb * Hh];           // fp16(h)
__device__ uint16_t g_Hlo[Ll * Bb * Hh];           // fp16(h - fp16(h))  (subnormal ok)
__device__ uint16_t g_Ahi[(size_t)Tt * Bb * Ee];   // fp16(A)   (input-GEMM A)
__device__ uint16_t g_Alo[(size_t)Tt * Bb * Ee];   // bf16(A - fp16(A))
__device__ uint16_t g_Whi[(size_t)G3 * Ee];        // fp16(W_ih)
__device__ uint16_t g_Wbf[(size_t)G3 * Ee];        // bf16(W_ih)
__device__ uint16_t g_Whh16[(size_t)Ll * G3 * Hh]; // fp16(W_hh)

// Grid barrier state (monotonic release counter)
__device__ unsigned g_bar_arrive = 0;
__device__ unsigned g_bar_release = 0;

// ---------------------------------------------------------------------------
// PTX helpers
// ---------------------------------------------------------------------------
__device__ __forceinline__ uint32_t smem_u32(const void* p) {
    uint32_t a;
    asm("{ .reg .u64 t; cvta.to.shared.u64 t, %1; cvt.u32.u64 %0, t; }" : "=r"(a) : "l"(p));
    return a;
}
#define LDSM_X4(r0, r1, r2, r3, a) \
    asm volatile("ldmatrix.sync.aligned.m8n8.x4.shared.b16 {%0,%1,%2,%3}, [%4];" \
                 : "=r"(r0), "=r"(r1), "=r"(r2), "=r"(r3) : "r"(a))
#define MMA_BF16(d, a, b0, b1) \
    asm volatile("mma.sync.aligned.m16n8k16.row.col.f32.bf16.bf16.f32 " \
                 "{%0,%1,%2,%3}, {%4,%5,%6,%7}, {%8,%9}, {%0,%1,%2,%3};" \
                 : "+f"((d)[0]), "+f"((d)[1]), "+f"((d)[2]), "+f"((d)[3]) \
                 : "r"((a)[0]), "r"((a)[1]), "r"((a)[2]), "r"((a)[3]), \
                   "r"(b0), "r"(b1))
#define MMA_F16(d, a, b0, b1) \
    asm volatile("mma.sync.aligned.m16n8k16.row.col.f32.f16.f16.f32 " \
                 "{%0,%1,%2,%3}, {%4,%5,%6,%7}, {%8,%9}, {%0,%1,%2,%3};" \
                 : "+f"((d)[0]), "+f"((d)[1]), "+f"((d)[2]), "+f"((d)[3]) \
                 : "r"((a)[0]), "r"((a)[1]), "r"((a)[2]), "r"((a)[3]), \
                   "r"(b0), "r"(b1))
#define CP_ASYNC16(dst, src) \
    asm volatile("cp.async.cg.shared.global [%0], [%1], 16;" :: "r"(dst), "l"(src) : "memory")
#define CP_COMMIT  asm volatile("cp.async.commit_group;" ::: "memory")
#define CP_WAIT1   asm volatile("cp.async.wait_group 1;" ::: "memory")
#define CP_WAIT0   asm volatile("cp.async.wait_group 0;" ::: "memory")

__device__ __forceinline__ uint32_t pk_bf2(float lo, float hi) {
    __nv_bfloat162 t = __floats2bfloat162_rn(lo, hi);
    return *reinterpret_cast<uint32_t*>(&t);
}
__device__ __forceinline__ uint32_t pk_h2(float lo, float hi) {
    __half2 t = __floats2half2_rn(lo, hi);
    return *reinterpret_cast<uint32_t*>(&t);
}

// Split grid barrier (monotonic counter; base read at kernel start)
__device__ __forceinline__ void bar_arrive() {
    __syncthreads();
    if (threadIdx.x == 0) {
        __threadfence();
        unsigned a = atomicAdd(&g_bar_arrive, 1u);
        if (a == RGRID - 1) {
            g_bar_arrive = 0;
            __threadfence();
            atomicAdd(&g_bar_release, 1u);
        }
    }
}
__device__ __forceinline__ void bar_wait(unsigned target) {
    if (threadIdx.x == 0) {
        while ((int)(*(volatile unsigned*)&g_bar_release - target) < 0) __nanosleep(32);
        __threadfence();
    }
    __syncthreads();
}

// ---------------------------------------------------------------------------
// Embedding with fused fp16/bf16 split
// ---------------------------------------------------------------------------
__global__ void embed_split(const int* __restrict__ x, const float* __restrict__ emb) {
    int row = blockIdx.x;          // t*B + b
    int t = row / Bb;
    int b = row - t * Bb;
    int tok = x[b * Tt + t];
    float4 v = reinterpret_cast<const float4*>(emb + (size_t)tok * Ee)[threadIdx.x];
    float hx = __half2float(__float2half_rn(v.x));
    float hy = __half2float(__float2half_rn(v.y));
    float hz = __half2float(__float2half_rn(v.z));
    float hw = __half2float(__float2half_rn(v.w));
    uint2 wh = make_uint2(pk_h2(hx, hy), pk_h2(hz, hw));
    uint2 wl = make_uint2(pk_bf2(v.x - hx, v.y - hy), pk_bf2(v.z - hz, v.w - hw));
    size_t base = (size_t)row * Ee + threadIdx.x * 4;
    *reinterpret_cast<uint2*>(g_Ahi + base) = wh;
    *reinterpret_cast<uint2*>(g_Alo + base) = wl;
}

__global__ void init_h(const float* __restrict__ h0) {
    int i = blockIdx.x * blockDim.x + threadIdx.x;
    if (i < Ll * Bb * Hh) {
        float v = h0[i];
        g_h[i] = v;
        __half hh = __float2half_rn(v);
        float hf = __half2float(hh);
        __half lo = __float2half_rn(v - hf);
        g_Hhi[i] = *reinterpret_cast<uint16_t*>(&hh);
        g_Hlo[i] = *reinterpret_cast<uint16_t*>(&lo);
    }
}

__global__ void conv_split_W(const float* __restrict__ src) {
    size_t i = (size_t)blockIdx.x * 256 + threadIdx.x;
    float x = src[i];
    __half h = __float2half_rn(x);
    __nv_bfloat16 b = __float2bfloat16(x);
    g_Whi[i] = *reinterpret_cast<uint16_t*>(&h);
    g_Wbf[i] = *reinterpret_cast<uint16_t*>(&b);
}

__global__ void conv_whh16(const float* __restrict__ Whh) {
    size_t i = (size_t)blockIdx.x * 256 + threadIdx.x;
    __half h = __float2half_rn(Whh[i]);
    g_Whh16[i] = *reinterpret_cast<uint16_t*>(&h);
}

// ---------------------------------------------------------------------------
// 2-pass split TN GEMM via mma.sync, 3-stage cp.async pipeline (unchanged,
// passing since round 13).
// ---------------------------------------------------------------------------
extern __shared__ __align__(16) unsigned char s_raw[];

__global__ __launch_bounds__(256, 2) void gemm_gx_mma(const float* __restrict__ bias) {
    const int tid = threadIdx.x;
    const int wid = tid >> 5, lane = tid & 31;
    const int m0 = blockIdx.y * MT_M;
    const int n0 = blockIdx.x * MT_N;
    const int wm = (wid >> 2) * 64;
    const int wn = (wid & 3) * 32;

    const uint32_t sbase = smem_u32(s_raw);
    const int strow = tid >> 3;
    const int stcol = tid & 7;
    const int lrow = lane & 15;
    const int lcol = lane >> 4;

    float acc[4][4][4];
#pragma unroll
    for (int i = 0; i < 4; i++)
#pragma unroll
        for (int j = 0; j < 4; j++)
#pragma unroll
            for (int r = 0; r < 4; r++) acc[i][j][r] = 0.f;

    auto issue_chunk = [&](int c, int s) {
        int pass = c >> 4, cc = c & 15;
        const uint16_t* Asrc = pass ? g_Alo : g_Ahi;
        const uint16_t* Bsrc = pass ? g_Wbf : g_Whi;
#pragma unroll
        for (int i = 0; i < 4; i++) {
            int r = strow + 32 * i;
            const uint16_t* ga = Asrc + (size_t)(m0 + r) * Ee + cc * KCH + stcol * 8;
            const uint16_t* gb = Bsrc + (size_t)(n0 + r) * Ee + cc * KCH + stcol * 8;
            uint32_t off = (uint32_t)(r * PADU + stcol) * 16 + s * GSTG;
            CP_ASYNC16(sbase + off, ga);
            CP_ASYNC16(sbase + NSTAGE * GSTG + off, gb);
        }
    };

    issue_chunk(0, 0);
    CP_COMMIT;
    issue_chunk(1, 1);
    CP_COMMIT;

    const int NCH = NPASS * 16;      // 32
    for (int c = 0; c < NCH; c++) {
        if (c < NCH - 2) CP_WAIT1; else CP_WAIT0;
        __syncthreads();
        if (c < NCH - 2) {
            issue_chunk(c + 2, (c + 2) % NSTAGE);
            CP_COMMIT;
        }

        const uint32_t sa = sbase + (c % NSTAGE) * GSTG;
        const uint32_t sb = sbase + NSTAGE * GSTG + (c % NSTAGE) * GSTG;
#pragma unroll
        for (int k16 = 0; k16 < KCH / 16; k16++) {
            uint32_t af[4][4];
#pragma unroll
            for (int mt = 0; mt < 4; mt++) {
                uint32_t addr = sa + ((wm + mt * 16 + lrow) * PADU + k16 * 2 + lcol) * 16;
                LDSM_X4(af[mt][0], af[mt][1], af[mt][2], af[mt][3], addr);
            }
            uint32_t bf[2][4];
#pragma unroll
            for (int bt = 0; bt < 2; bt++) {
                uint32_t addr = sb + ((wn + bt * 16 + lrow) * PADU + k16 * 2 + lcol) * 16;
                LDSM_X4(bf[bt][0], bf[bt][1], bf[bt][2], bf[bt][3], addr);
            }
            if (c < 16) {
#pragma unroll
                for (int mt = 0; mt < 4; mt++)
#pragma unroll
                    for (int nt = 0; nt < 4; nt++) {
                        int bt = nt >> 1, lh = nt & 1;
                        MMA_F16(acc[mt][nt], af[mt], bf[bt][lh], bf[bt][lh + 2]);
                    }
            } else {
#pragma unroll
                for (int mt = 0; mt < 4; mt++)
#pragma unroll
                    for (int nt = 0; nt < 4; nt++) {
                        int bt = nt >> 1, lh = nt & 1;
                        MMA_BF16(acc[mt][nt], af[mt], bf[bt][lh], bf[bt][lh + 2]);
                    }
            }
        }
    }

    const int er = lane >> 2;
    const int ec = (lane & 3) * 2;
#pragma unroll
    for (int mt = 0; mt < 4; mt++) {
#pragma unroll
        for (int half = 0; half < 2; half++) {
            int grow = m0 + wm + mt * 16 + er + half * 8;
            size_t base = (size_t)grow * G3;
#pragma unroll
            for (int nt = 0; nt < 4; nt++) {
                int gcol = n0 + wn + nt * 8 + ec;
                float2 v;
                v.x = acc[mt][nt][half * 2 + 0] + bias[gcol];
                v.y = acc[mt][nt][half * 2 + 1] + bias[gcol + 1];
                *reinterpret_cast<float2*>(&g_gx[base + gcol]) = v;
            }
        }
    }
}

// ---------------------------------------------------------------------------
// Persistent recurrence, no-k-split edition.
// Block = (bh = bid&1, nt = bid>>1): batch rows bh*32..+32, col group nt:
//   cols {g*1024 + nt*16 + 0..15 : g = r,z,n}.
// Smem (229376 B, u4 offsets): sH16 @0 [32x128u4], sHlo @4096, sW @8192 [48x128u4].
// All rows XOR-swizzled: u4col ^= (row & 7).
// Per step: cp.async-pipelined staging (8 chunks of k=128) overlapped with
// 2-pass fp16 HMMA (full K) -> gh exchange in smem -> gates -> h write ->
// ONE grid barrier.
// ---------------------------------------------------------------------------
__global__ __launch_bounds__(256, 1) void gru_layer_persist(
    int l, const float* __restrict__ bhh_all, float* __restrict__ dout) {

    uint4* s4 = reinterpret_cast<uint4*>(s_raw);
    const uint32_t aH16 = smem_u32(s4);
    const uint32_t aHlo = aH16 + 4096 * 16;
    const uint32_t aW   = aH16 + 8192 * 16;
    float* ghs = reinterpret_cast<float*>(s4 + 4096);   // overlay on sHlo (dead after MMA)

    const int tid = threadIdx.x;
    const int bid = blockIdx.x;
    const int wid = tid >> 5, lane = tid & 31;
    const int bh = bid & 1;
    const int nt = bid >> 1;                 // 0..63

    const float* bhh = bhh_all + l * G3;
    const uint16_t* hb16 = g_Hhi + l * Bb * Hh;
    const uint16_t* hblo = g_Hlo + l * Bb * Hh;
    const uint16_t* Wsrc = g_Whh16 + (size_t)l * G3 * Hh;

    __shared__ unsigned s_base0;
    if (tid == 0) s_base0 = *(volatile unsigned*)&g_bar_release;

    // ---- startup: load W slice (48 rows: 3 gates x 16 cols) fp16, swizzled ----
    for (int f = tid; f < 48 * 128; f += 256) {
        int r = f >> 7;                       // smem row 0..47
        int c = f & 127;                      // u4 col
        int gr = (r >> 4) * 1024 + nt * 16 + (r & 15);   // global W_hh row
        uint32_t dst = ((uint32_t)(r * 128 + (c ^ (r & 7)))) * 16;
        CP_ASYNC16(aW + dst, Wsrc + (size_t)gr * Hh + c * 8);
    }
    CP_COMMIT;
    CP_WAIT0;
    __syncthreads();
    const unsigned bar_base = s_base0;
    unsigned gen = 0;

    // MMA warp assignment: 6 warps: wm in {0,16} (m16 over 32 b-rows),
    // wn in {0,16,32} (n16 over 48 W rows). Warps 6,7 idle in MMA.
    const int wm = (wid & 1) * 16;
    const int wn = (wid >> 1) * 16;
    const bool mma_w = (wid < 6);
    const int lrow = lane & 15;
    const int lcol = lane >> 4;
    const int er = lane >> 2;
    const int ec = (lane & 3) * 2;

    // gate-phase constants: 2 consecutive elements per thread
    int bl_[2], cl_[2], b_[2], j_[2];
    float br_[2], bz_[2], bn_[2];
#pragma unroll
    for (int ei = 0; ei < 2; ei++) {
        int idx = tid * 2 + ei;               // 0..511
        bl_[ei] = idx >> 4;                   // 0..31
        cl_[ei] = idx & 15;                   // 0..15
        b_[ei] = bh * 32 + bl_[ei];
        j_[ei] = nt * 16 + cl_[ei];
        br_[ei] = bhh[j_[ei]];
        bz_[ei] = bhh[Hh + j_[ei]];
        bn_[ei] = bhh[2 * Hh + j_[ei]];
    }

    for (int t = 0; t < Tt; t++) {
        // ---- stage chunk helper: chunk c covers k [c*128, c*128+128) ----
        auto stage_chunk = [&](int c) {
#pragma unroll
            for (int i = 0; i < 2; i++) {
                int f = tid + i * 256;        // 0..511
                int r = f >> 4;               // 0..31
                int ci = f & 15;
                uint32_t col = (uint32_t)(c * 16 + ci);
                uint32_t dst = ((uint32_t)(r * 128 + (col ^ (r & 7)))) * 16;
                size_t src = (size_t)(bh * 32 + r) * Hh + c * 128 + ci * 8;
                CP_ASYNC16(aH16 + dst, hb16 + src);
                CP_ASYNC16(aHlo + dst, hblo + src);
            }
        };

        stage_chunk(0); CP_COMMIT;
        stage_chunk(1); CP_COMMIT;

        // prefetch gate inputs (long-latency; overlap with staging+MMA)
        float xr_[2], xz_[2], xn_[2], hold_[2];
#pragma unroll
        for (int ei = 0; ei < 2; ei++) {
            size_t gxb = ((size_t)t * Bb + b_[ei]) * G3;
            xr_[ei] = g_gx[gxb + j_[ei]];
            xz_[ei] = g_gx[gxb + Hh + j_[ei]];
            xn_[ei] = g_gx[gxb + 2 * Hh + j_[ei]];
            hold_[ei] = g_h[l * Bb * Hh + b_[ei] * Hh + j_[ei]];
        }

        float acc[2][4];
#pragma unroll
        for (int j = 0; j < 2; j++)
#pragma unroll
            for (int r = 0; r < 4; r++) acc[j][r] = 0.f;

        for (int c = 0; c < 8; c++) {
            if (c < 7) CP_WAIT1; else CP_WAIT0;
            __syncthreads();
            if (c < 6) { stage_chunk(c + 2); CP_COMMIT; }

            if (mma_w) {
#pragma unroll
                for (int kk = 0; kk < 8; kk++) {
                    int colu = (c * 8 + kk) * 2 + lcol;
                    // B frags (W, fp16) — shared by both passes
                    uint32_t bfr[4];
                    {
                        int row = wn + lrow;
                        uint32_t addr = aW + ((uint32_t)(row * 128 + (colu ^ (row & 7)))) * 16;
                        LDSM_X4(bfr[0], bfr[1], bfr[2], bfr[3], addr);
                    }
                    // pass 0: h16
                    {
                        int row = wm + lrow;
                        uint32_t addr = aH16 + ((uint32_t)(row * 128 + (colu ^ (row & 7)))) * 16;
                        uint32_t af[4];
                        LDSM_X4(af[0], af[1], af[2], af[3], addr);
                        MMA_F16(acc[0], af, bfr[0], bfr[2]);
                        MMA_F16(acc[1], af, bfr[1], bfr[3]);
                    }
                    // pass 1: hlo (fp16, subnormal-range)
                    {
                        int row = wm + lrow;
                        uint32_t addr = aHlo + ((uint32_t)(row * 128 + (colu ^ (row & 7)))) * 16;
                        uint32_t af[4];
                        LDSM_X4(af[0], af[1], af[2], af[3], addr);
                        MMA_F16(acc[0], af, bfr[0], bfr[2]);
                        MMA_F16(acc[1], af, bfr[1], bfr[3]);
                    }
                }
            }
        }

        __syncthreads();   // all MMA reads of sHlo done -> ghs overlay safe

        // ---- dump gh to smem exchange buffer: ghs[b_local][col<48], stride 49 ----
        if (mma_w) {
#pragma unroll
            for (int lh = 0; lh < 2; lh++)
#pragma unroll
                for (int half = 0; half < 2; half++) {
                    int row = wm + er + half * 8;
                    int col = wn + lh * 8 + ec;
                    ghs[row * 49 + col]     = acc[lh][half * 2 + 0];
                    ghs[row * 49 + col + 1] = acc[lh][half * 2 + 1];
                }
        }
        __syncthreads();

        // ---- gates + state update (no partials, no second barrier) ----
#pragma unroll
        for (int ei = 0; ei < 2; ei++) {
            int bl = bl_[ei], cl = cl_[ei];
            float hr = ghs[bl * 49 + cl]      + br_[ei];
            float hz = ghs[bl * 49 + cl + 16] + bz_[ei];
            float hn = ghs[bl * 49 + cl + 32] + bn_[ei];

            float rg = 1.f / (1.f + expf(-(xr_[ei] + hr)));
            float zg = 1.f / (1.f + expf(-(xz_[ei] + hz)));
            float ng = tanhf(xn_[ei] + rg * hn);

            float hnew = (1.f - zg) * ng + zg * hold_[ei];
            int e = b_[ei] * Hh + j_[ei];
            g_h[l * Bb * Hh + e] = hnew;

            // producer-side splits: fp16 hi (both uses), fp16 lo (recurrence),
            // bf16 lo (layer-1 input GEMM)
            __half hh = __float2half_rn(hnew);
            float hf = __half2float(hh);
            __half lo16 = __float2half_rn(hnew - hf);
            g_Hhi[l * Bb * Hh + e] = *reinterpret_cast<uint16_t*>(&hh);
            g_Hlo[l * Bb * Hh + e] = *reinterpret_cast<uint16_t*>(&lo16);

            if (l == 0) {
                __nv_bfloat16 lob = __float2bfloat16(hnew - hf);
                size_t arow = ((size_t)t * Bb + b_[ei]) * Ee + j_[ei];
                g_Ahi[arow] = *reinterpret_cast<uint16_t*>(&hh);
                g_Alo[arow] = *reinterpret_cast<uint16_t*>(&lob);
                dout[HIDS_OFF + ((size_t)b_[ei] * Tt + t) * Hh + j_[ei]] = hnew;
            }
        }

        bar_arrive();
        ++gen;
        bar_wait(bar_base + gen);
    }
}

__global__ void finalize(float* __restrict__ dout) {
    int i = blockIdx.x * blockDim.x + threadIdx.x;
    float h0f = g_h[i];
    float h1f = g_h[Bb * Hh + i];
    dout[OUT_OFF + i] = h1f;
    dout[HID_OFF + i] = h0f;
    dout[HID_OFF + Bb * Hh + i] = h1f;
}

// ---------------------------------------------------------------------------
extern "C" void kernel_launch(void* const* d_in, const int* in_sizes, int n_in,
                              void* d_out, int out_size) {
    const int*   x   = (const int*)d_in[0];
    const float* h0  = (const float*)d_in[1];
    const float* emb = (const float*)d_in[2];
    const float* Wih = (const float*)d_in[3];
    const float* Whh = (const float*)d_in[4];
    const float* bih = (const float*)d_in[5];
    const float* bhh = (const float*)d_in[6];
    float* out = (float*)d_out;

    const int gemm_smem = 2 * NSTAGE * GSTG;    // 110592
    const int rec_smem = 14336 * 16;            // 229376 (sH16 64K + sHlo 64K + sW 96K)
    cudaFuncSetAttribute(gemm_gx_mma,
                         cudaFuncAttributeMaxDynamicSharedMemorySize, gemm_smem);
    cudaFuncSetAttribute(gru_layer_persist,
                         cudaFuncAttributeMaxDynamicSharedMemorySize, rec_smem);

    init_h<<<(Ll * Bb * Hh + 255) / 256, 256>>>(h0);
    embed_split<<<Tt * Bb, Ee / 4>>>(x, emb);
    conv_whh16<<<(Ll * G3 * Hh) / 256, 256>>>(Whh);

    dim3 tgrid(G3 / MT_N, (Tt * Bb) / MT_M);    // (24, 256)
    const int nW = (G3 * Ee) / 256;

    // Layer 0
    conv_split_W<<<nW, 256>>>(Wih);
    gemm_gx_mma<<<tgrid, 256, gemm_smem>>>(bih);
    gru_layer_persist<<<RGRID, 256, rec_smem>>>(0, bhh, out);

    // Layer 1 (A = fp16/bf16 split of layer-0 states, written by the gate phase)
    conv_split_W<<<nW, 256>>>(Wih + (size_t)G3 * Ee);
    gemm_gx_mma<<<tgrid, 256, gemm_smem>>>(bih + G3);
    gru_layer_persist<<<RGRID, 256, rec_smem>>>(1, bhh, out);

    finalize<<<(Bb * Hh) / 256, 256>>>(out);
}